// round 10
// baseline (speedup 1.0000x reference)
#include <cuda_runtime.h>

// MKMMD loss, B=256, D=256, n=512, KERNEL_MUL=2, KERNEL_NUM=5, FIX_SIGMA=None.
// SINGLE fused kernel, 128 blocks x 256 threads (1 block/SM, one wave).
// Phase bodies are verbatim from the passing R9 two-kernel version; the only
// new machinery is the in-kernel handoff, built on the canonical
// threadfence-before-counter pattern (R8 failed because an empty asm
// "consume" emits no SASS and orders nothing).
//
//  Phase A: per-column sums (padded, one 128B line/column) + weighted S2.
//           writes -> __threadfence(all threads) -> syncthreads -> tid0:
//           ws2 atomic -> __threadfence -> counter bump.
//  Publish: last arriver fences (acquire), recomputes bandwidth exactly as
//           R9-K1, then stores inv16 (>0) into 128 per-block padded slots.
//  Poll:    each block volatile-spins on ITS OWN slot (value = payload; no
//           consumer fence, no contention, volatile prevents hoisting).
//  Phase B: diffs + prefix scan (before poll, overlaps), 1 exp + 4 squarings,
//           fenced DOUBLE atomic tail (float final accum loses ~3e-3: R4).
//
// Math:
//  - sum(l2_cum) over (n,n,D) = sum_f (D-f) * (2n*S2_f - 2*S1_f^2)
//  - only 4B=1024 (row,row) pairs contribute
//  - exp(-x/(bw_base*2^k)) = e4^(2^(4-k)), e4 = exp(-x/(16*bw_base))
//  - inv16 = (n*n-n)/(4*bwsum) = 65408/bwsum

#define BB 256
#define DD 256

#define NB  128
#define NT  256
#define NW  8
#define ROWS_PB 4
#define PAD 32                          // 32 floats = one 128B line

__device__ float        g_s1p[DD * PAD];
__device__ float        g_ws2f;
__device__ float        g_bw[NB * PAD]; // per-block inv16 slots (0 = not ready)
__device__ double       g_acc;
__device__ unsigned int g_done1;
__device__ unsigned int g_done2;

__global__ void __launch_bounds__(NT, 1) mkmmd_fused(
    const float* __restrict__ src, const float* __restrict__ tgt,
    float* __restrict__ out) {
    const int tid  = threadIdx.x;
    const int warp = tid >> 5;
    const int lane = tid & 31;
    const int bid  = blockIdx.x;

    __shared__ float sh_red[NW];
    __shared__ float sh_inv;
    __shared__ bool  sh_last;

    // ---------------- prologue: issue pair loads (latency overlap) ----------
    const int p   = bid * NW + warp;            // 0..1023; grp uniform per blk
    const int grp = p >> 8;
    const int i   = p & (BB - 1);
    const int j   = (i + 1) & (BB - 1);

    const float* pa;
    const float* pb;
    float sign;
    if (grp == 0)      { pa = src + i * DD; pb = src + j * DD; sign =  1.f; }
    else if (grp == 1) { pa = tgt + i * DD; pb = tgt + j * DD; sign =  1.f; }
    else if (grp == 2) { pa = src + i * DD; pb = tgt + j * DD; sign = -1.f; }
    else               { pa = src + j * DD; pb = tgt + i * DD; sign = -1.f; }

    const float4* a4 = reinterpret_cast<const float4*>(pa) + lane * 2;
    const float4* b4 = reinterpret_cast<const float4*>(pb) + lane * 2;
    float4 a0 = a4[0], a1 = a4[1];
    float4 b0 = b4[0], b1 = b4[1];

    // ---------------- phase A: stats (R9-K1 body) ---------------------------
    {
        const int r0 = bid * ROWS_PB;
        float s1 = 0.f, s2 = 0.f;
#pragma unroll
        for (int k = 0; k < ROWS_PB; ++k) {
            int r = r0 + k;
            const float* row = (r < BB) ? (src + r * DD) : (tgt + (r - BB) * DD);
            float v = row[tid];
            s1 += v;
            s2 = fmaf(v, v, s2);
        }
        atomicAdd(&g_s1p[tid * PAD], s1);

        float term = (float)(DD - tid) * s2;
#pragma unroll
        for (int off = 16; off > 0; off >>= 1)
            term += __shfl_xor_sync(0xffffffffu, term, off);
        if (lane == 0) sh_red[warp] = term;

        __threadfence();                // each thread: column atomic performed
        __syncthreads();                // join fences + sh_red ready

        if (tid == 0) {
            float bsum = 0.f;
#pragma unroll
            for (int w = 0; w < NW; ++w) bsum += sh_red[w];
            atomicAdd(&g_ws2f, bsum);
            __threadfence();            // ws2 add performed before counter
            unsigned int c = atomicAdd(&g_done1, 1u);
            sh_last = (c == (unsigned int)(NB - 1));
        }
        __syncthreads();
    }

    // ---------------- publisher: bandwidth -> per-block slots ---------------
    if (sh_last) {
        __threadfence();                // acquire: see all payload atomics
        float s  = __ldcg(&g_s1p[tid * PAD]);
        float tm = (float)(DD - tid) * s * s;
#pragma unroll
        for (int off = 16; off > 0; off >>= 1)
            tm += __shfl_xor_sync(0xffffffffu, tm, off);
        if (lane == 0) sh_red[warp] = tm;
        __syncthreads();
        if (tid == 0) {
            float s1sq = 0.f;
#pragma unroll
            for (int w = 0; w < NW; ++w) s1sq += sh_red[w];
            float ws2   = atomicAdd(&g_ws2f, 0.f);
            float bwsum = 1024.f * ws2 - 2.f * s1sq;   // 2n*ws2 - 2*s1sq
            sh_inv = 65408.f / bwsum;                  // (n^2-n)/(4*bwsum), >0
        }
        __syncthreads();
        if (tid < NB)
            *((volatile float*)&g_bw[tid * PAD]) = sh_inv;
    }

    // ---------------- diffs + prefix scan (independent of bandwidth) --------
    float sq[8];
    {
        float d0 = a0.x - b0.x, d1 = a0.y - b0.y, d2 = a0.z - b0.z, d3 = a0.w - b0.w;
        float d4 = a1.x - b1.x, d5 = a1.y - b1.y, d6 = a1.z - b1.z, d7 = a1.w - b1.w;
        sq[0] = d0 * d0; sq[1] = d1 * d1; sq[2] = d2 * d2; sq[3] = d3 * d3;
        sq[4] = d4 * d4; sq[5] = d5 * d5; sq[6] = d6 * d6; sq[7] = d7 * d7;
    }
    float run = 0.f;
#pragma unroll
    for (int k = 0; k < 8; ++k) { run += sq[k]; sq[k] = run; }

    float pref = run;
#pragma unroll
    for (int off = 1; off < 32; off <<= 1) {
        float y = __shfl_up_sync(0xffffffffu, pref, off);
        if (lane >= off) pref += y;
    }
    const float excl = pref - run;

    // ---------------- poll own slot (value IS the payload) ------------------
    float inv16;
    {
        volatile float* slot = (volatile float*)&g_bw[bid * PAD];
        while ((inv16 = *slot) == 0.f) { }
    }

    // ---------------- Gaussian multi-kernel sum (R9-K2 body) ----------------
    float lacc = 0.f;
#pragma unroll
    for (int k = 0; k < 8; ++k) {
        float y  = (sq[k] + excl) * inv16;
        float e4 = __expf(-y);
        float s  = e4;
        float t2 = e4 * e4;  s += t2;
        t2 *= t2;            s += t2;
        t2 *= t2;            s += t2;
        t2 *= t2;            s += t2;
        lacc += s;
    }
    lacc *= sign;

#pragma unroll
    for (int off = 16; off > 0; off >>= 1)
        lacc += __shfl_xor_sync(0xffffffffu, lacc, off);

    if (lane == 0) sh_red[warp] = lacc;
    __syncthreads();

    // ---------------- fenced tail: double atomic + counter ------------------
    if (tid == 0) {
        float bsum = 0.f;
#pragma unroll
        for (int w = 0; w < NW; ++w) bsum += sh_red[w];
        atomicAdd(&g_acc, (double)bsum);
        __threadfence();                // payload performed before counter
        unsigned int c = atomicAdd(&g_done2, 1u);
        sh_last = (c == (unsigned int)(NB - 1));
    }
    __syncthreads();

    // ---------------- final block: output + full state reset ----------------
    if (sh_last) {
        if (tid == 0) {
            __threadfence();            // acquire
            double tot = atomicAdd(&g_acc, 0.0);
            out[0] = (float)(tot * (1.0 / 65536.0));   // / (B*D)
            g_acc   = 0.0;
            g_ws2f  = 0.f;
            g_done1 = 0u;
            g_done2 = 0u;
        }
        g_s1p[tid * PAD] = 0.f;                        // reset for replay
        if (tid < NB) g_bw[tid * PAD] = 0.f;           // all polls already done
    }
}

extern "C" void kernel_launch(void* const* d_in, const int* in_sizes, int n_in,
                              void* d_out, int out_size) {
    const float* src = (const float*)d_in[0];
    const float* tgt = (const float*)d_in[1];
    float* out = (float*)d_out;
    (void)in_sizes; (void)n_in; (void)out_size;

    mkmmd_fused<<<NB, NT>>>(src, tgt, out);
}